// round 15
// baseline (speedup 1.0000x reference)
#include <cuda_runtime.h>
#include <cuda_fp16.h>
#include <cstdint>

#define Bn 2
#define Hn 16
#define Sn 2048
#define Dn 1024
#define HDn 64
#define SC2 (0.125f * 1.44269504088896340736f)

typedef unsigned long long u64;
typedef unsigned int u32;

#define XN2 2097152   // 4096*512
#define WN2 524288    // 1024*512
static __device__ u32 g_xh[XN2];
static __device__ u32 g_wsh[4 * WN2], g_wsl[4 * WN2];
static __device__ u32 g_qh[XN2];
static __device__ u32 g_kh[XN2], g_kl[XN2];
static __device__ u32 g_vh[XN2];
static __device__ u32 g_aoh[XN2];

__device__ __forceinline__ float ex2f_(float x) {
    float y; asm("ex2.approx.f32 %0, %1;" : "=f"(y) : "f"(x)); return y;
}
__device__ __forceinline__ u32 smem_u32(const void* p) {
    u32 a; asm("{ .reg .u64 t; cvta.to.shared.u64 t, %1; cvt.u32.u64 %0, t; }" : "=r"(a) : "l"(p));
    return a;
}
__device__ __forceinline__ u32 f16pack(float a, float b) {
    __half2 h = __floats2half2_rn(a, b);
    return *(u32*)&h;
}
__device__ __forceinline__ float f16lo(u32 h) {
    return __half2float(__ushort_as_half((unsigned short)(h & 0xffffu)));
}
__device__ __forceinline__ float f16hi(u32 h) {
    return __half2float(__ushort_as_half((unsigned short)(h >> 16)));
}
__device__ __forceinline__ void mma16816(float* d, const u32* a, const u32* b) {
    asm volatile(
        "mma.sync.aligned.m16n8k16.row.col.f32.f16.f16.f32 "
        "{%0,%1,%2,%3}, {%4,%5,%6,%7}, {%8,%9}, {%0,%1,%2,%3};"
        : "+f"(d[0]), "+f"(d[1]), "+f"(d[2]), "+f"(d[3])
        : "r"(a[0]), "r"(a[1]), "r"(a[2]), "r"(a[3]), "r"(b[0]), "r"(b[1]));
}
__device__ __forceinline__ void ldsm4(u32* r, u32 addr) {
    asm volatile("ldmatrix.sync.aligned.m8n8.x4.shared.b16 {%0,%1,%2,%3}, [%4];"
        : "=r"(r[0]), "=r"(r[1]), "=r"(r[2]), "=r"(r[3]) : "r"(addr));
}
__device__ __forceinline__ void ldsm4t(u32* r, u32 addr) {
    asm volatile("ldmatrix.sync.aligned.m8n8.x4.trans.shared.b16 {%0,%1,%2,%3}, [%4];"
        : "=r"(r[0]), "=r"(r[1]), "=r"(r[2]), "=r"(r[3]) : "r"(addr));
}
__device__ __forceinline__ void cpa16(u32 dst, const void* src) {
    asm volatile("cp.async.cg.shared.global [%0], [%1], 16;" :: "r"(dst), "l"(src));
}
#define CP_COMMIT() asm volatile("cp.async.commit_group;" ::: "memory")
#define WAITG0() asm volatile("cp.async.wait_group 0;" ::: "memory")
#define WAITG1() asm volatile("cp.async.wait_group 1;" ::: "memory")

// ---------------------------------------------------------------------------
struct CArgs {
    const float* src[5];
    u32* dh[5];
    u32* dl[5];
    int n2[5];
};
__global__ void __launch_bounds__(256) split_k(CArgs ca)
{
    const int z = blockIdx.y;
    const float* __restrict__ s = ca.src[z];
    u32* __restrict__ dh = ca.dh[z];
    u32* __restrict__ dl = ca.dl[z];
    const int n2 = ca.n2[z];
    for (int i = blockIdx.x * 256 + threadIdx.x; i < n2; i += gridDim.x * 256) {
        float2 v = *(const float2*)(s + 2 * i);
        u32 h = f16pack(v.x, v.y);
        dh[i] = h;
        if (dl) dl[i] = f16pack(v.x - f16lo(h), v.y - f16hi(h));
    }
}

// ---------------------------------------------------------------------------
// fp16 2-product GEMM (R10 exact: K-chunk 32, 3-stage cp.async, 2 CTA/SM).
// ---------------------------------------------------------------------------
#define GKH 40
#define GT_AH 0
#define GT_WH 10240
#define GT_WL 20480
#define GSTAGE 30720
#define GNS 3
#define GEMM_SMEM (512 + GNS * GSTAGE)   // 92672

struct GArgs {
    const u32 *Ah, *Wh, *Wl;
    const float* bias[3];
    u32 *oh[3];
    float* C;
};

template <int OUT_SPLIT>
__global__ void __launch_bounds__(256, 2) gemm_mma(GArgs ga)
{
    extern __shared__ char smem[];
    const u32 sbase = smem_u32(smem);
    float* sbias = (float*)smem;

    const int z    = blockIdx.z;
    const int tid  = threadIdx.x;
    const int lane = tid & 31;
    const int wid  = tid >> 5;
    const int n0   = blockIdx.x * 128;
    const int m0   = blockIdx.y * 128;
    const int wm   = (wid & 1) * 64;
    const int wn   = (wid >> 1) * 32;

    const u32* __restrict__ Ah = ga.Ah;
    const u32* __restrict__ Wh = ga.Wh + (size_t)z * WN2;
    const u32* __restrict__ Wl = ga.Wl + (size_t)z * WN2;

    if (tid < 128) sbias[tid] = ga.bias[z][n0 + tid];

    float acc[4][4][4];
#pragma unroll
    for (int i = 0; i < 4; i++)
#pragma unroll
        for (int j = 0; j < 4; j++)
#pragma unroll
            for (int c = 0; c < 4; c++) acc[i][j][c] = 0.f;

    const int lrow = tid >> 1;
    const int lh   = tid & 1;
    const size_t abase = (size_t)(m0 + lrow) * 512 + lh * 8;
    const size_t wbase = (size_t)(n0 + lrow) * 512 + lh * 8;
    const u32 sobase = lrow * 80 + lh * 32;

    auto load_stage = [&](int t, int slot) {
        const u32 so = sbase + 512 + slot * GSTAGE + sobase;
        const size_t ka = abase + t * 16;
        const size_t kw = wbase + t * 16;
        cpa16(so + GT_AH,      Ah + ka);
        cpa16(so + GT_AH + 16, Ah + ka + 4);
        cpa16(so + GT_WH,      Wh + kw);
        cpa16(so + GT_WH + 16, Wh + kw + 4);
        cpa16(so + GT_WL,      Wl + kw);
        cpa16(so + GT_WL + 16, Wl + kw + 4);
    };

    const int a_r  = wm + (lane & 15);
    const int b_r4 = wn + (lane & 7) + ((lane & 16) ? 8 : 0);

    auto mma_stage = [&](int slot) {
        const u32 sb = sbase + 512 + slot * GSTAGE;
#pragma unroll
        for (int ks = 0; ks < 2; ks++) {
            const int acol  = ks * 16 + ((lane & 16) ? 8 : 0);
            const int bcol4 = ks * 16 + ((lane & 8) ? 8 : 0);
            u32 ah[4][4];
#pragma unroll
            for (int mt = 0; mt < 4; mt++)
                ldsm4(ah[mt], sb + GT_AH + (u32)((a_r + mt * 16) * (GKH * 2) + acol * 2));
            u32 bhq[2][4], blq[2][4];
#pragma unroll
            for (int np = 0; np < 2; np++) {
                u32 o = (u32)((b_r4 + np * 16) * (GKH * 2) + bcol4 * 2);
                ldsm4(bhq[np], sb + GT_WH + o);
                ldsm4(blq[np], sb + GT_WL + o);
            }
#pragma unroll
            for (int mt = 0; mt < 4; mt++)
#pragma unroll
                for (int nt = 0; nt < 4; nt++) {
                    const u32* bh_ = &bhq[nt >> 1][(nt & 1) * 2];
                    const u32* bl_ = &blq[nt >> 1][(nt & 1) * 2];
                    mma16816(acc[mt][nt], ah[mt], bh_);
                    mma16816(acc[mt][nt], ah[mt], bl_);
                }
        }
    };

    const int NT = Dn / 32;
    load_stage(0, 0); CP_COMMIT();
    load_stage(1, 1); CP_COMMIT();

    for (int t = 0; t < NT; t++) {
        if (t + 1 < NT) { WAITG1(); } else { WAITG0(); }
        __syncthreads();
        if (t + 2 < NT) { load_stage(t + 2, (t + 2) % GNS); CP_COMMIT(); }
        mma_stage(t % GNS);
    }

    const int g   = lane >> 2;
    const int tig = lane & 3;
    const float osc = (OUT_SPLIT && z == 0) ? SC2 : 1.0f;
#pragma unroll
    for (int mt = 0; mt < 4; mt++) {
#pragma unroll
        for (int nt = 0; nt < 4; nt++) {
            int coll = wn + nt * 8 + tig * 2;
            int col  = n0 + coll;
            float bx = sbias[coll], by = sbias[coll + 1];
            int r0 = m0 + wm + mt * 16 + g;
            int r1 = r0 + 8;
            float x0 = (acc[mt][nt][0] + bx) * osc, y0 = (acc[mt][nt][1] + by) * osc;
            float x1 = (acc[mt][nt][2] + bx) * osc, y1 = (acc[mt][nt][3] + by) * osc;
            if (OUT_SPLIT) {
                u32* oh = ga.oh[z];
                u32* ol = (z == 1) ? g_kl : nullptr;
                int h = col >> 6, cu = (col & 63) >> 1;
                {
                    int b = r0 >> 11, s = r0 & 2047;
                    size_t idx = ((size_t)((b << 4) + h) * Sn + s) * 32 + cu;
                    u32 hh = f16pack(x0, y0);
                    oh[idx] = hh;
                    if (ol) ol[idx] = f16pack(x0 - f16lo(hh), y0 - f16hi(hh));
                }
                {
                    int b = r1 >> 11, s = r1 & 2047;
                    size_t idx = ((size_t)((b << 4) + h) * Sn + s) * 32 + cu;
                    u32 hh = f16pack(x1, y1);
                    oh[idx] = hh;
                    if (ol) ol[idx] = f16pack(x1 - f16lo(hh), y1 - f16hi(hh));
                }
            } else {
                *(float2*)&ga.C[(size_t)r0 * Dn + col] = make_float2(x0, y0);
                *(float2*)&ga.C[(size_t)r1 * Dn + col] = make_float2(x1, y1);
            }
        }
    }
}

// ---------------------------------------------------------------------------
// Attention: paired q-tiles (qb = j and 15-j) per CTA sharing one K/V stream,
// now with 3-stage K/V ring (prefetch depth 2, WAITG1). One sync per k-tile.
// ---------------------------------------------------------------------------
#define PADH 72
#define PADB (PADH * 2)
#define TILE_HB (128 * PADB)            // 18432
#define QA_OFF 0
#define QB_OFF 18432
#define KS(st) (36864 + (st) * 36864)   // 3 stages: hi +0, lo +18432
#define VS(st) (147456 + (st) * 18432)  // 3 stages: hi only
#define ATTN_SMEM 202752

__global__ void __launch_bounds__(256) attn_k(
    const u32* __restrict__ qh,
    const u32* __restrict__ kh, const u32* __restrict__ kl,
    const u32* __restrict__ vh,
    float* __restrict__ wout, u32* __restrict__ aoh)
{
    extern __shared__ char smem[];
    const u32 sb = smem_u32(smem);

    const int tid  = threadIdx.x;
    const int lane = tid & 31;
    const int wid  = tid >> 5;
    const int qbA  = blockIdx.x;          // 0..7
    const int qbB  = 15 - qbA;            // 15..8
    const int bh   = blockIdx.y;
    const int qA0  = qbA * 128;
    const int qB0  = qbB * 128;
    const int g    = lane >> 2;
    const int tig  = lane & 3;
    const float NEG_INF = __int_as_float(0xff800000);

    const int lrow = tid >> 1;
    const int lseg = (tid & 1) * 16;

    auto load_q = [&](int q0, u32 qoff) {
        const size_t gidx = ((size_t)bh * Sn + q0 + lrow) * 32 + lseg;
        const u32 so = sb + qoff + lrow * PADB + lseg * 4;
#pragma unroll
        for (int j = 0; j < 4; j++) cpa16(so + j * 16, qh + gidx + j * 4);
    };
    auto load_kv = [&](int kt) {                 // K(hi+lo) + V(hi), stage kt%3
        const size_t gidx = ((size_t)bh * Sn + kt * 128 + lrow) * 32 + lseg;
        const int st = kt % 3;
        const u32 sok = sb + KS(st) + lrow * PADB + lseg * 4;
        const u32 sov = sb + VS(st) + lrow * PADB + lseg * 4;
#pragma unroll
        for (int j = 0; j < 4; j++) {
            cpa16(sok + j * 16,           kh + gidx + j * 4);
            cpa16(sok + TILE_HB + j * 16, kl + gidx + j * 4);
            cpa16(sov + j * 16,           vh + gidx + j * 4);
        }
    };

    const int r0l = wid * 16 + g;

    auto qk_scores = [&](u32 qoff, int kt, bool diag, float acc[16][4]) {
#pragma unroll
        for (int nt = 0; nt < 16; nt++)
#pragma unroll
            for (int c = 0; c < 4; c++) acc[nt][c] = 0.f;
        const u32 a_base  = sb + qoff + (wid * 16 + (lane & 15)) * PADB + (((lane >> 4) << 3)) * 2;
        const u32 b_base4 = sb + KS(kt % 3) + ((lane & 7) + ((lane & 16) ? 8 : 0)) * PADB
                          + (((lane >> 3) & 1) << 3) * 2;
#pragma unroll
        for (int kc = 0; kc < 4; kc++) {
            u32 ah[4];
            ldsm4(ah, a_base + kc * 32);
#pragma unroll
            for (int np = 0; np < 8; np++) {
                u32 bhq[4], blq[4];
                u32 bo = b_base4 + np * 16 * PADB + kc * 32;
                ldsm4(bhq, bo);
                ldsm4(blq, bo + TILE_HB);
                mma16816(acc[2 * np],     ah, bhq);
                mma16816(acc[2 * np],     ah, blq);
                mma16816(acc[2 * np + 1], ah, bhq + 2);
                mma16816(acc[2 * np + 1], ah, blq + 2);
            }
        }
        if (diag) {
#pragma unroll
            for (int nt = 0; nt < 16; nt++) {
                int c0 = nt * 8 + tig * 2;
                if (c0 > r0l)         acc[nt][0] = NEG_INF;
                if (c0 + 1 > r0l)     acc[nt][1] = NEG_INF;
                if (c0 > r0l + 8)     acc[nt][2] = NEG_INF;
                if (c0 + 1 > r0l + 8) acc[nt][3] = NEG_INF;
            }
        }
    };

    // prologue: (QA + QB + K0/V0) group 0, (K1/V1) group 1
    load_q(qA0, QA_OFF);
    load_q(qB0, QB_OFF);
    load_kv(0);
    CP_COMMIT();
    if (qbB >= 1) { load_kv(1); CP_COMMIT(); }

    float rsA0 = 0.f, rsA1 = 0.f, rsB0 = 0.f, rsB1 = 0.f;
    float oaccA[8][4], oaccB[8][4];
#pragma unroll
    for (int v = 0; v < 8; v++)
#pragma unroll
        for (int c = 0; c < 4; c++) { oaccA[v][c] = 0.f; oaccB[v][c] = 0.f; }

    float* wpA0 = wout + (size_t)bh * Sn * Sn + (size_t)(qA0 + r0l) * Sn;
    float* wpA1 = wpA0 + 8 * Sn;
    float* wpB0 = wout + (size_t)bh * Sn * Sn + (size_t)(qB0 + r0l) * Sn;
    float* wpB1 = wpB0 + 8 * Sn;

    auto process = [&](u32 qoff, int kt, bool diag, float* wp0, float* wp1,
                       float (&oacc)[8][4], float& rs0, float& rs1) {
        float acc[16][4];
        qk_scores(qoff, kt, diag, acc);
#pragma unroll
        for (int nt = 0; nt < 16; nt++) {
            float p0 = ex2f_(acc[nt][0]);
            float p1 = ex2f_(acc[nt][1]);
            float p2 = ex2f_(acc[nt][2]);
            float p3 = ex2f_(acc[nt][3]);
            rs0 += p0 + p1; rs1 += p2 + p3;
            acc[nt][0] = p0; acc[nt][1] = p1; acc[nt][2] = p2; acc[nt][3] = p3;
            int c0 = kt * 128 + nt * 8 + tig * 2;
            *(float2*)(wp0 + c0) = make_float2(p0, p1);
            *(float2*)(wp1 + c0) = make_float2(p2, p3);
        }
        const u32 v_base4 = sb + VS(kt % 3) + (lane & 15) * PADB + ((lane & 16) ? 16 : 0);
#pragma unroll
        for (int kc = 0; kc < 8; kc++) {
            u32 aph[4];
            aph[0] = f16pack(acc[2 * kc][0],     acc[2 * kc][1]);
            aph[1] = f16pack(acc[2 * kc][2],     acc[2 * kc][3]);
            aph[2] = f16pack(acc[2 * kc + 1][0], acc[2 * kc + 1][1]);
            aph[3] = f16pack(acc[2 * kc + 1][2], acc[2 * kc + 1][3]);
            const u32 vb = v_base4 + kc * 16 * PADB;
#pragma unroll
            for (int vp = 0; vp < 4; vp++) {
                u32 vh4[4];
                ldsm4t(vh4, vb + vp * 32);
                mma16816(oacc[2 * vp],     aph, vh4);
                mma16816(oacc[2 * vp + 1], aph, vh4 + 2);
            }
        }
    };

    for (int kt = 0; kt <= qbB; kt++) {
        if (kt + 1 <= qbB) { WAITG1(); } else { WAITG0(); }
        __syncthreads();
        if (kt + 2 <= qbB) { load_kv(kt + 2); CP_COMMIT(); }
        process(QB_OFF, kt, kt == qbB, wpB0, wpB1, oaccB, rsB0, rsB1);
        if (kt <= qbA)
            process(QA_OFF, kt, kt == qbA, wpA0, wpA1, oaccA, rsA0, rsA1);
    }

    // row-sum reductions (quad) and output scaling
    rsA0 += __shfl_xor_sync(0xffffffffu, rsA0, 1);
    rsA0 += __shfl_xor_sync(0xffffffffu, rsA0, 2);
    rsA1 += __shfl_xor_sync(0xffffffffu, rsA1, 1);
    rsA1 += __shfl_xor_sync(0xffffffffu, rsA1, 2);
    rsB0 += __shfl_xor_sync(0xffffffffu, rsB0, 1);
    rsB0 += __shfl_xor_sync(0xffffffffu, rsB0, 2);
    rsB1 += __shfl_xor_sync(0xffffffffu, rsB1, 1);
    rsB1 += __shfl_xor_sync(0xffffffffu, rsB1, 2);
    const float ilA0 = 1.0f / rsA0, ilA1 = 1.0f / rsA1;
    const float ilB0 = 1.0f / rsB0, ilB1 = 1.0f / rsB1;

#pragma unroll
    for (int vt = 0; vt < 8; vt++) {
        oaccA[vt][0] *= ilA0; oaccA[vt][1] *= ilA0;
        oaccA[vt][2] *= ilA1; oaccA[vt][3] *= ilA1;
        oaccB[vt][0] *= ilB0; oaccB[vt][1] *= ilB0;
        oaccB[vt][2] *= ilB1; oaccB[vt][3] *= ilB1;
    }

    __syncthreads();
    float* sil = (float*)smem;                    // [0..127]=A rows, [128..255]=B rows
    if (tig == 0) {
        sil[wid * 16 + g]           = ilA0;
        sil[wid * 16 + 8 + g]       = ilA1;
        sil[128 + wid * 16 + g]     = ilB0;
        sil[128 + wid * 16 + 8 + g] = ilB1;
    }
    __syncthreads();

    // in-place weight normalization for both tiles
    {
        const int row = tid >> 1;
        {
            const int ncol = (qbA + 1) * 128;
            const int half = (tid & 1) * (ncol >> 1);
            const float ilr = sil[row];
            float* p = wout + (size_t)bh * Sn * Sn + (size_t)(qA0 + row) * Sn + half;
            for (int c = 0; c < (ncol >> 1); c += 4) {
                float4 v = *(float4*)(p + c);
                v.x *= ilr; v.y *= ilr; v.z *= ilr; v.w *= ilr;
                __stcs((float4*)(p + c), v);
            }
        }
        {
            const int ncol = (qbB + 1) * 128;
            const int half = (tid & 1) * (ncol >> 1);
            const float ilr = sil[128 + row];
            float* p = wout + (size_t)bh * Sn * Sn + (size_t)(qB0 + row) * Sn + half;
            for (int c = 0; c < (ncol >> 1); c += 4) {
                float4 v = *(float4*)(p + c);
                v.x *= ilr; v.y *= ilr; v.z *= ilr; v.w *= ilr;
                __stcs((float4*)(p + c), v);
            }
        }
    }

    // zero-fill masked regions for both tiles
    {
        const int row = tid >> 1;
        const float4 z4 = make_float4(0.f, 0.f, 0.f, 0.f);
        {
            const int zw = (15 - qbA) * 128;
            const int half = (tid & 1) * (zw >> 1);
            float* p = wout + (size_t)bh * Sn * Sn + (size_t)(qA0 + row) * Sn
                     + (qbA + 1) * 128 + half;
            for (int c = 0; c < (zw >> 1); c += 4) __stcs((float4*)(p + c), z4);
        }
        if (qbB < 15) {
            const int zw = (15 - qbB) * 128;
            const int half = (tid & 1) * (zw >> 1);
            float* p = wout + (size_t)bh * Sn * Sn + (size_t)(qB0 + row) * Sn
                     + (qbB + 1) * 128 + half;
            for (int c = 0; c < (zw >> 1); c += 4) __stcs((float4*)(p + c), z4);
        }
    }

    // attention outputs -> fp16 hi flat [4096][512 u32]
    {
        const size_t tA0 = ((size_t)(bh >> 4) * Sn + qA0 + r0l) * 512 + (bh & 15) * 32;
        const size_t tA1 = tA0 + 8 * 512;
        const size_t tB0 = ((size_t)(bh >> 4) * Sn + qB0 + r0l) * 512 + (bh & 15) * 32;
        const size_t tB1 = tB0 + 8 * 512;
#pragma unroll
        for (int vt = 0; vt < 8; vt++) {
            int c = vt * 4 + tig;
            aoh[tA0 + c] = f16pack(oaccA[vt][0], oaccA[vt][1]);
            aoh[tA1 + c] = f16pack(oaccA[vt][2], oaccA[vt][3]);
            aoh[tB0 + c] = f16pack(oaccB[vt][0], oaccB[vt][1]);
            aoh[tB1 + c] = f16pack(oaccB[vt][2], oaccB[vt][3]);
        }
    }
}

// ---------------------------------------------------------------------------
extern "C" void kernel_launch(void* const* d_in, const int* in_sizes, int n_in,
                              void* d_out, int out_size)
{
    const float* query = (const float*)d_in[0];
    const float* Wq    = (const float*)d_in[1];
    const float* bq    = (const float*)d_in[2];
    const float* Wk    = (const float*)d_in[3];
    const float* bk    = (const float*)d_in[4];
    const float* Wv    = (const float*)d_in[5];
    const float* bv    = (const float*)d_in[6];
    const float* Wo    = (const float*)d_in[7];
    const float* bo    = (const float*)d_in[8];

    float* out = (float*)d_out;
    float* wts = out + (size_t)Bn * Sn * Dn;

    u32 *xh, *wsh, *wsl, *qh, *kh, *kl, *vh, *aoh;
    cudaGetSymbolAddress((void**)&xh,  g_xh);
    cudaGetSymbolAddress((void**)&wsh, g_wsh); cudaGetSymbolAddress((void**)&wsl, g_wsl);
    cudaGetSymbolAddress((void**)&qh,  g_qh);
    cudaGetSymbolAddress((void**)&kh,  g_kh);  cudaGetSymbolAddress((void**)&kl,  g_kl);
    cudaGetSymbolAddress((void**)&vh,  g_vh);
    cudaGetSymbolAddress((void**)&aoh, g_aoh);

    cudaFuncSetAttribute(attn_k, cudaFuncAttributeMaxDynamicSharedMemorySize, ATTN_SMEM);
    cudaFuncSetAttribute(gemm_mma<1>, cudaFuncAttributeMaxDynamicSharedMemorySize, GEMM_SMEM);
    cudaFuncSetAttribute(gemm_mma<0>, cudaFuncAttributeMaxDynamicSharedMemorySize, GEMM_SMEM);

    CArgs ca;
    ca.src[0] = query; ca.dh[0] = xh;            ca.dl[0] = nullptr;        ca.n2[0] = XN2;
    ca.src[1] = Wq;    ca.dh[1] = wsh;           ca.dl[1] = wsl;            ca.n2[1] = WN2;
    ca.src[2] = Wk;    ca.dh[2] = wsh + WN2;     ca.dl[2] = wsl + WN2;      ca.n2[2] = WN2;
    ca.src[3] = Wv;    ca.dh[3] = wsh + 2 * WN2; ca.dl[3] = wsl + 2 * WN2;  ca.n2[3] = WN2;
    ca.src[4] = Wo;    ca.dh[4] = wsh + 3 * WN2; ca.dl[4] = wsl + 3 * WN2;  ca.n2[4] = WN2;
    split_k<<<dim3(1024, 5), 256>>>(ca);

    GArgs qkv;
    qkv.Ah = xh; qkv.Wh = wsh; qkv.Wl = wsl;
    qkv.bias[0] = bq; qkv.bias[1] = bk; qkv.bias[2] = bv;
    qkv.oh[0] = qh; qkv.oh[1] = kh; qkv.oh[2] = vh;
    qkv.C = nullptr;
    gemm_mma<1><<<dim3(Dn / 128, (Bn * Sn) / 128, 3), 256, GEMM_SMEM>>>(qkv);

    attn_k<<<dim3(8, Bn * Hn), 256, ATTN_SMEM>>>(
        qh, kh, kl, vh, wts, aoh);

    GArgs og;
    og.Ah = aoh; og.Wh = wsh + 3 * WN2; og.Wl = wsl + 3 * WN2;
    og.bias[0] = bo; og.bias[1] = bo; og.bias[2] = bo;
    og.oh[0] = og.oh[1] = og.oh[2] = nullptr;
    og.C = out;
    gemm_mma<0><<<dim3(Dn / 128, (Bn * Sn) / 128, 1), 256, GEMM_SMEM>>>(og);
}

// round 16
// speedup vs baseline: 1.1525x; 1.1525x over previous
#include <cuda_runtime.h>
#include <cuda_fp16.h>
#include <cstdint>

#define Bn 2
#define Hn 16
#define Sn 2048
#define Dn 1024
#define HDn 64
#define SC2 (0.125f * 1.44269504088896340736f)

typedef unsigned long long u64;
typedef unsigned int u32;

#define XN2 2097152   // 4096*512
#define WN2 524288    // 1024*512
static __device__ u32 g_xh[XN2];
static __device__ u32 g_wsh[4 * WN2], g_wsl[4 * WN2];
static __device__ u32 g_qh[XN2];
static __device__ u32 g_kh[XN2], g_kl[XN2];
static __device__ u32 g_vh[XN2];
static __device__ u32 g_aoh[XN2];

__device__ __forceinline__ float ex2f_(float x) {
    float y; asm("ex2.approx.f32 %0, %1;" : "=f"(y) : "f"(x)); return y;
}
__device__ __forceinline__ u32 smem_u32(const void* p) {
    u32 a; asm("{ .reg .u64 t; cvta.to.shared.u64 t, %1; cvt.u32.u64 %0, t; }" : "=r"(a) : "l"(p));
    return a;
}
__device__ __forceinline__ u32 f16pack(float a, float b) {
    __half2 h = __floats2half2_rn(a, b);
    return *(u32*)&h;
}
__device__ __forceinline__ float f16lo(u32 h) {
    return __half2float(__ushort_as_half((unsigned short)(h & 0xffffu)));
}
__device__ __forceinline__ float f16hi(u32 h) {
    return __half2float(__ushort_as_half((unsigned short)(h >> 16)));
}
__device__ __forceinline__ void mma16816(float* d, const u32* a, const u32* b) {
    asm volatile(
        "mma.sync.aligned.m16n8k16.row.col.f32.f16.f16.f32 "
        "{%0,%1,%2,%3}, {%4,%5,%6,%7}, {%8,%9}, {%0,%1,%2,%3};"
        : "+f"(d[0]), "+f"(d[1]), "+f"(d[2]), "+f"(d[3])
        : "r"(a[0]), "r"(a[1]), "r"(a[2]), "r"(a[3]), "r"(b[0]), "r"(b[1]));
}
__device__ __forceinline__ void ldsm4(u32* r, u32 addr) {
    asm volatile("ldmatrix.sync.aligned.m8n8.x4.shared.b16 {%0,%1,%2,%3}, [%4];"
        : "=r"(r[0]), "=r"(r[1]), "=r"(r[2]), "=r"(r[3]) : "r"(addr));
}
__device__ __forceinline__ void ldsm4t(u32* r, u32 addr) {
    asm volatile("ldmatrix.sync.aligned.m8n8.x4.trans.shared.b16 {%0,%1,%2,%3}, [%4];"
        : "=r"(r[0]), "=r"(r[1]), "=r"(r[2]), "=r"(r[3]) : "r"(addr));
}
__device__ __forceinline__ void cpa16(u32 dst, const void* src) {
    asm volatile("cp.async.cg.shared.global [%0], [%1], 16;" :: "r"(dst), "l"(src));
}
#define CP_COMMIT() asm volatile("cp.async.commit_group;" ::: "memory")
#define WAITG0() asm volatile("cp.async.wait_group 0;" ::: "memory")
#define WAITG1() asm volatile("cp.async.wait_group 1;" ::: "memory")

// ---------------------------------------------------------------------------
struct CArgs {
    const float* src[5];
    u32* dh[5];
    u32* dl[5];
    int n2[5];
};
__global__ void __launch_bounds__(256) split_k(CArgs ca)
{
    const int z = blockIdx.y;
    const float* __restrict__ s = ca.src[z];
    u32* __restrict__ dh = ca.dh[z];
    u32* __restrict__ dl = ca.dl[z];
    const int n2 = ca.n2[z];
    for (int i = blockIdx.x * 256 + threadIdx.x; i < n2; i += gridDim.x * 256) {
        float2 v = *(const float2*)(s + 2 * i);
        u32 h = f16pack(v.x, v.y);
        dh[i] = h;
        if (dl) dl[i] = f16pack(v.x - f16lo(h), v.y - f16hi(h));
    }
}

// ---------------------------------------------------------------------------
// fp16 2-product GEMM (R10 exact: K-chunk 32, 3-stage cp.async, 2 CTA/SM).
// ---------------------------------------------------------------------------
#define GKH 40
#define GT_AH 0
#define GT_WH 10240
#define GT_WL 20480
#define GSTAGE 30720
#define GNS 3
#define GEMM_SMEM (512 + GNS * GSTAGE)   // 92672

struct GArgs {
    const u32 *Ah, *Wh, *Wl;
    const float* bias[3];
    u32 *oh[3];
    float* C;
};

template <int OUT_SPLIT>
__global__ void __launch_bounds__(256, 2) gemm_mma(GArgs ga)
{
    extern __shared__ char smem[];
    const u32 sbase = smem_u32(smem);
    float* sbias = (float*)smem;

    const int z    = blockIdx.z;
    const int tid  = threadIdx.x;
    const int lane = tid & 31;
    const int wid  = tid >> 5;
    const int n0   = blockIdx.x * 128;
    const int m0   = blockIdx.y * 128;
    const int wm   = (wid & 1) * 64;
    const int wn   = (wid >> 1) * 32;

    const u32* __restrict__ Ah = ga.Ah;
    const u32* __restrict__ Wh = ga.Wh + (size_t)z * WN2;
    const u32* __restrict__ Wl = ga.Wl + (size_t)z * WN2;

    if (tid < 128) sbias[tid] = ga.bias[z][n0 + tid];

    float acc[4][4][4];
#pragma unroll
    for (int i = 0; i < 4; i++)
#pragma unroll
        for (int j = 0; j < 4; j++)
#pragma unroll
            for (int c = 0; c < 4; c++) acc[i][j][c] = 0.f;

    const int lrow = tid >> 1;
    const int lh   = tid & 1;
    const size_t abase = (size_t)(m0 + lrow) * 512 + lh * 8;
    const size_t wbase = (size_t)(n0 + lrow) * 512 + lh * 8;
    const u32 sobase = lrow * 80 + lh * 32;

    auto load_stage = [&](int t, int slot) {
        const u32 so = sbase + 512 + slot * GSTAGE + sobase;
        const size_t ka = abase + t * 16;
        const size_t kw = wbase + t * 16;
        cpa16(so + GT_AH,      Ah + ka);
        cpa16(so + GT_AH + 16, Ah + ka + 4);
        cpa16(so + GT_WH,      Wh + kw);
        cpa16(so + GT_WH + 16, Wh + kw + 4);
        cpa16(so + GT_WL,      Wl + kw);
        cpa16(so + GT_WL + 16, Wl + kw + 4);
    };

    const int a_r  = wm + (lane & 15);
    const int b_r4 = wn + (lane & 7) + ((lane & 16) ? 8 : 0);

    auto mma_stage = [&](int slot) {
        const u32 sb = sbase + 512 + slot * GSTAGE;
#pragma unroll
        for (int ks = 0; ks < 2; ks++) {
            const int acol  = ks * 16 + ((lane & 16) ? 8 : 0);
            const int bcol4 = ks * 16 + ((lane & 8) ? 8 : 0);
            u32 ah[4][4];
#pragma unroll
            for (int mt = 0; mt < 4; mt++)
                ldsm4(ah[mt], sb + GT_AH + (u32)((a_r + mt * 16) * (GKH * 2) + acol * 2));
            u32 bhq[2][4], blq[2][4];
#pragma unroll
            for (int np = 0; np < 2; np++) {
                u32 o = (u32)((b_r4 + np * 16) * (GKH * 2) + bcol4 * 2);
                ldsm4(bhq[np], sb + GT_WH + o);
                ldsm4(blq[np], sb + GT_WL + o);
            }
#pragma unroll
            for (int mt = 0; mt < 4; mt++)
#pragma unroll
                for (int nt = 0; nt < 4; nt++) {
                    const u32* bh_ = &bhq[nt >> 1][(nt & 1) * 2];
                    const u32* bl_ = &blq[nt >> 1][(nt & 1) * 2];
                    mma16816(acc[mt][nt], ah[mt], bh_);
                    mma16816(acc[mt][nt], ah[mt], bl_);
                }
        }
    };

    const int NT = Dn / 32;
    load_stage(0, 0); CP_COMMIT();
    load_stage(1, 1); CP_COMMIT();

    for (int t = 0; t < NT; t++) {
        if (t + 1 < NT) { WAITG1(); } else { WAITG0(); }
        __syncthreads();
        if (t + 2 < NT) { load_stage(t + 2, (t + 2) % GNS); CP_COMMIT(); }
        mma_stage(t % GNS);
    }

    const int g   = lane >> 2;
    const int tig = lane & 3;
    const float osc = (OUT_SPLIT && z == 0) ? SC2 : 1.0f;
#pragma unroll
    for (int mt = 0; mt < 4; mt++) {
#pragma unroll
        for (int nt = 0; nt < 4; nt++) {
            int coll = wn + nt * 8 + tig * 2;
            int col  = n0 + coll;
            float bx = sbias[coll], by = sbias[coll + 1];
            int r0 = m0 + wm + mt * 16 + g;
            int r1 = r0 + 8;
            float x0 = (acc[mt][nt][0] + bx) * osc, y0 = (acc[mt][nt][1] + by) * osc;
            float x1 = (acc[mt][nt][2] + bx) * osc, y1 = (acc[mt][nt][3] + by) * osc;
            if (OUT_SPLIT) {
                u32* oh = ga.oh[z];
                u32* ol = (z == 1) ? g_kl : nullptr;
                int h = col >> 6, cu = (col & 63) >> 1;
                {
                    int b = r0 >> 11, s = r0 & 2047;
                    size_t idx = ((size_t)((b << 4) + h) * Sn + s) * 32 + cu;
                    u32 hh = f16pack(x0, y0);
                    oh[idx] = hh;
                    if (ol) ol[idx] = f16pack(x0 - f16lo(hh), y0 - f16hi(hh));
                }
                {
                    int b = r1 >> 11, s = r1 & 2047;
                    size_t idx = ((size_t)((b << 4) + h) * Sn + s) * 32 + cu;
                    u32 hh = f16pack(x1, y1);
                    oh[idx] = hh;
                    if (ol) ol[idx] = f16pack(x1 - f16lo(hh), y1 - f16hi(hh));
                }
            } else {
                *(float2*)&ga.C[(size_t)r0 * Dn + col] = make_float2(x0, y0);
                *(float2*)&ga.C[(size_t)r1 * Dn + col] = make_float2(x1, y1);
            }
        }
    }
}

// ---------------------------------------------------------------------------
// Attention: paired q-tiles (qb=j, 15-j) per CTA (R14 layout), EXACT two-phase:
//   phase 1: stream K, QK + exp, row sums only (no stores, no V).
//   phase 2: recompute identical scores, write FINAL normalized weights once
//            (.cs, never re-read), fused PV.  No fixup pass.
// ---------------------------------------------------------------------------
#define PADH 72
#define PADB (PADH * 2)
#define TILE_HB (128 * PADB)            // 18432
#define QA_OFF 0
#define QB_OFF 18432
#define KS(st) (36864 + (st) * 36864)   // hi +0, lo +18432
#define VS(st) (110592 + (st) * 18432)
#define ATTN_SMEM 147456

__global__ void __launch_bounds__(256) attn_k(
    const u32* __restrict__ qh,
    const u32* __restrict__ kh, const u32* __restrict__ kl,
    const u32* __restrict__ vh,
    float* __restrict__ wout, u32* __restrict__ aoh)
{
    extern __shared__ char smem[];
    const u32 sb = smem_u32(smem);

    const int tid  = threadIdx.x;
    const int lane = tid & 31;
    const int wid  = tid >> 5;
    const int qbA  = blockIdx.x;          // 0..7
    const int qbB  = 15 - qbA;            // 15..8
    const int bh   = blockIdx.y;
    const int qA0  = qbA * 128;
    const int qB0  = qbB * 128;
    const int g    = lane >> 2;
    const int tig  = lane & 3;
    const float NEG_INF = __int_as_float(0xff800000);

    const int lrow = tid >> 1;
    const int lseg = (tid & 1) * 16;

    auto load_q = [&](int q0, u32 qoff) {
        const size_t gidx = ((size_t)bh * Sn + q0 + lrow) * 32 + lseg;
        const u32 so = sb + qoff + lrow * PADB + lseg * 4;
#pragma unroll
        for (int j = 0; j < 4; j++) cpa16(so + j * 16, qh + gidx + j * 4);
    };
    auto load_k2 = [&](int kt) {
        const size_t gidx = ((size_t)bh * Sn + kt * 128 + lrow) * 32 + lseg;
        const u32 so = sb + KS(kt & 1) + lrow * PADB + lseg * 4;
#pragma unroll
        for (int j = 0; j < 4; j++) {
            cpa16(so + j * 16,           kh + gidx + j * 4);
            cpa16(so + TILE_HB + j * 16, kl + gidx + j * 4);
        }
    };
    auto load_v1 = [&](int kt) {
        const size_t gidx = ((size_t)bh * Sn + kt * 128 + lrow) * 32 + lseg;
        const u32 so = sb + VS(kt & 1) + lrow * PADB + lseg * 4;
#pragma unroll
        for (int j = 0; j < 4; j++) cpa16(so + j * 16, vh + gidx + j * 4);
    };

    const int r0l = wid * 16 + g;

    auto qk_scores = [&](u32 qoff, int kt, bool diag, float acc[16][4]) {
#pragma unroll
        for (int nt = 0; nt < 16; nt++)
#pragma unroll
            for (int c = 0; c < 4; c++) acc[nt][c] = 0.f;
        const u32 a_base  = sb + qoff + (wid * 16 + (lane & 15)) * PADB + (((lane >> 4) << 3)) * 2;
        const u32 b_base4 = sb + KS(kt & 1) + ((lane & 7) + ((lane & 16) ? 8 : 0)) * PADB
                          + (((lane >> 3) & 1) << 3) * 2;
#pragma unroll
        for (int kc = 0; kc < 4; kc++) {
            u32 ah[4];
            ldsm4(ah, a_base + kc * 32);
#pragma unroll
            for (int np = 0; np < 8; np++) {
                u32 bhq[4], blq[4];
                u32 bo = b_base4 + np * 16 * PADB + kc * 32;
                ldsm4(bhq, bo);
                ldsm4(blq, bo + TILE_HB);
                mma16816(acc[2 * np],     ah, bhq);
                mma16816(acc[2 * np],     ah, blq);
                mma16816(acc[2 * np + 1], ah, bhq + 2);
                mma16816(acc[2 * np + 1], ah, blq + 2);
            }
        }
        if (diag) {
#pragma unroll
            for (int nt = 0; nt < 16; nt++) {
                int c0 = nt * 8 + tig * 2;
                if (c0 > r0l)         acc[nt][0] = NEG_INF;
                if (c0 + 1 > r0l)     acc[nt][1] = NEG_INF;
                if (c0 > r0l + 8)     acc[nt][2] = NEG_INF;
                if (c0 + 1 > r0l + 8) acc[nt][3] = NEG_INF;
            }
        }
    };

    float rsA0 = 0.f, rsA1 = 0.f, rsB0 = 0.f, rsB1 = 0.f;

    auto sum_only = [&](u32 qoff, int kt, bool diag, float& rs0, float& rs1) {
        float acc[16][4];
        qk_scores(qoff, kt, diag, acc);
#pragma unroll
        for (int nt = 0; nt < 16; nt++) {
            rs0 += ex2f_(acc[nt][0]) + ex2f_(acc[nt][1]);
            rs1 += ex2f_(acc[nt][2]) + ex2f_(acc[nt][3]);
        }
    };

    // ---- Phase 1: row sums (K only, no V, no stores) ----
    load_q(qA0, QA_OFF);
    load_q(qB0, QB_OFF);
    load_k2(0);
    CP_COMMIT();

    for (int kt = 0; kt <= qbB; kt++) {
        WAITG0();
        __syncthreads();
        if (kt < qbB) { load_k2(kt + 1); CP_COMMIT(); }
        sum_only(QB_OFF, kt, kt == qbB, rsB0, rsB1);
        if (kt <= qbA)
            sum_only(QA_OFF, kt, kt == qbA, rsA0, rsA1);
    }

    rsA0 += __shfl_xor_sync(0xffffffffu, rsA0, 1);
    rsA0 += __shfl_xor_sync(0xffffffffu, rsA0, 2);
    rsA1 += __shfl_xor_sync(0xffffffffu, rsA1, 1);
    rsA1 += __shfl_xor_sync(0xffffffffu, rsA1, 2);
    rsB0 += __shfl_xor_sync(0xffffffffu, rsB0, 1);
    rsB0 += __shfl_xor_sync(0xffffffffu, rsB0, 2);
    rsB1 += __shfl_xor_sync(0xffffffffu, rsB1, 1);
    rsB1 += __shfl_xor_sync(0xffffffffu, rsB1, 2);
    const float ilA0 = 1.0f / rsA0, ilA1 = 1.0f / rsA1;
    const float ilB0 = 1.0f / rsB0, ilB1 = 1.0f / rsB1;

    // ---- Phase 2: normalized weights (write-once, .cs) + PV ----
    __syncthreads();
    load_k2(0);
    load_v1(0);
    CP_COMMIT();

    float oaccA[8][4], oaccB[8][4];
#pragma unroll
    for (int v = 0; v < 8; v++)
#pragma unroll
        for (int c = 0; c < 4; c++) { oaccA[v][c] = 0.f; oaccB[v][c] = 0.f; }

    float* wpA0 = wout + (size_t)bh * Sn * Sn + (size_t)(qA0 + r0l) * Sn;
    float* wpA1 = wpA0 + 8 * Sn;
    float* wpB0 = wout + (size_t)bh * Sn * Sn + (size_t)(qB0 + r0l) * Sn;
    float* wpB1 = wpB0 + 8 * Sn;

    auto process = [&](u32 qoff, int kt, bool diag, float* wp0, float* wp1,
                       float (&oacc)[8][4], float il0, float il1) {
        float acc[16][4];
        qk_scores(qoff, kt, diag, acc);
#pragma unroll
        for (int nt = 0; nt < 16; nt++) {
            float p0 = ex2f_(acc[nt][0]);
            float p1 = ex2f_(acc[nt][1]);
            float p2 = ex2f_(acc[nt][2]);
            float p3 = ex2f_(acc[nt][3]);
            acc[nt][0] = p0; acc[nt][1] = p1; acc[nt][2] = p2; acc[nt][3] = p3;
            int c0 = kt * 128 + nt * 8 + tig * 2;
            __stcs((float2*)(wp0 + c0), make_float2(p0 * il0, p1 * il0));
            __stcs((float2*)(wp1 + c0), make_float2(p2 * il1, p3 * il1));
        }
        const u32 v_base4 = sb + VS(kt & 1) + (lane & 15) * PADB + ((lane & 16) ? 16 : 0);
#pragma unroll
        for (int kc = 0; kc < 8; kc++) {
            u32 aph[4];
            aph[0] = f16pack(acc[2 * kc][0],     acc[2 * kc][1]);
            aph[1] = f16pack(acc[2 * kc][2],     acc[2 * kc][3]);
            aph[2] = f16pack(acc[2 * kc + 1][0], acc[2 * kc + 1][1]);
            aph[3] = f16pack(acc[2 * kc + 1][2], acc[2 * kc + 1][3]);
            const u32 vb = v_base4 + kc * 16 * PADB;
#pragma unroll
            for (int vp = 0; vp < 4; vp++) {
                u32 vh4[4];
                ldsm4t(vh4, vb + vp * 32);
                mma16816(oacc[2 * vp],     aph, vh4);
                mma16816(oacc[2 * vp + 1], aph, vh4 + 2);
            }
        }
    };

    for (int kt = 0; kt <= qbB; kt++) {
        WAITG0();
        __syncthreads();
        if (kt < qbB) {
            load_k2(kt + 1);
            load_v1(kt + 1);
            CP_COMMIT();
        }
        process(QB_OFF, kt, kt == qbB, wpB0, wpB1, oaccB, ilB0, ilB1);
        if (kt <= qbA)
            process(QA_OFF, kt, kt == qbA, wpA0, wpA1, oaccA, ilA0, ilA1);
    }

    // scale outputs (PV used unnormalized p)
#pragma unroll
    for (int vt = 0; vt < 8; vt++) {
        oaccA[vt][0] *= ilA0; oaccA[vt][1] *= ilA0;
        oaccA[vt][2] *= ilA1; oaccA[vt][3] *= ilA1;
        oaccB[vt][0] *= ilB0; oaccB[vt][1] *= ilB0;
        oaccB[vt][2] *= ilB1; oaccB[vt][3] *= ilB1;
    }

    // zero-fill masked regions for both tiles
    {
        const int row = tid >> 1;
        const float4 z4 = make_float4(0.f, 0.f, 0.f, 0.f);
        {
            const int zw = (15 - qbA) * 128;
            const int half = (tid & 1) * (zw >> 1);
            float* p = wout + (size_t)bh * Sn * Sn + (size_t)(qA0 + row) * Sn
                     + (qbA + 1) * 128 + half;
            for (int c = 0; c < (zw >> 1); c += 4) __stcs((float4*)(p + c), z4);
        }
        if (qbB < 15) {
            const int zw = (15 - qbB) * 128;
            const int half = (tid & 1) * (zw >> 1);
            float* p = wout + (size_t)bh * Sn * Sn + (size_t)(qB0 + row) * Sn
                     + (qbB + 1) * 128 + half;
            for (int c = 0; c < (zw >> 1); c += 4) __stcs((float4*)(p + c), z4);
        }
    }

    // attention outputs -> fp16 hi flat [4096][512 u32]
    {
        const size_t tA0 = ((size_t)(bh >> 4) * Sn + qA0 + r0l) * 512 + (bh & 15) * 32;
        const size_t tA1 = tA0 + 8 * 512;
        const size_t tB0 = ((size_t)(bh >> 4) * Sn + qB0 + r0l) * 512 + (bh & 15) * 32;
        const size_t tB1 = tB0 + 8 * 512;
#pragma unroll
        for (int vt = 0; vt < 8; vt++) {
            int c = vt * 4 + tig;
            aoh[tA0 + c] = f16pack(oaccA[vt][0], oaccA[vt][1]);
            aoh[tA1 + c] = f16pack(oaccA[vt][2], oaccA[vt][3]);
            aoh[tB0 + c] = f16pack(oaccB[vt][0], oaccB[vt][1]);
            aoh[tB1 + c] = f16pack(oaccB[vt][2], oaccB[vt][3]);
        }
    }
}

// ---------------------------------------------------------------------------
extern "C" void kernel_launch(void* const* d_in, const int* in_sizes, int n_in,
                              void* d_out, int out_size)
{
    const float* query = (const float*)d_in[0];
    const float* Wq    = (const float*)d_in[1];
    const float* bq    = (const float*)d_in[2];
    const float* Wk    = (const float*)d_in[3];
    const float* bk    = (const float*)d_in[4];
    const float* Wv    = (const float*)d_in[5];
    const float* bv    = (const float*)d_in[6];
    const float* Wo    = (const float*)d_in[7];
    const float* bo    = (const float*)d_in[8];

    float* out = (float*)d_out;
    float* wts = out + (size_t)Bn * Sn * Dn;

    u32 *xh, *wsh, *wsl, *qh, *kh, *kl, *vh, *aoh;
    cudaGetSymbolAddress((void**)&xh,  g_xh);
    cudaGetSymbolAddress((void**)&wsh, g_wsh); cudaGetSymbolAddress((void**)&wsl, g_wsl);
    cudaGetSymbolAddress((void**)&qh,  g_qh);
    cudaGetSymbolAddress((void**)&kh,  g_kh);  cudaGetSymbolAddress((void**)&kl,  g_kl);
    cudaGetSymbolAddress((void**)&vh,  g_vh);
    cudaGetSymbolAddress((void**)&aoh, g_aoh);

    cudaFuncSetAttribute(attn_k, cudaFuncAttributeMaxDynamicSharedMemorySize, ATTN_SMEM);
    cudaFuncSetAttribute(gemm_mma<1>, cudaFuncAttributeMaxDynamicSharedMemorySize, GEMM_SMEM);
    cudaFuncSetAttribute(gemm_mma<0>, cudaFuncAttributeMaxDynamicSharedMemorySize, GEMM_SMEM);

    CArgs ca;
    ca.src[0] = query; ca.dh[0] = xh;            ca.dl[0] = nullptr;        ca.n2[0] = XN2;
    ca.src[1] = Wq;    ca.dh[1] = wsh;           ca.dl[1] = wsl;            ca.n2[1] = WN2;
    ca.src[2] = Wk;    ca.dh[2] = wsh + WN2;     ca.dl[2] = wsl + WN2;      ca.n2[2] = WN2;
    ca.src[3] = Wv;    ca.dh[3] = wsh + 2 * WN2; ca.dl[3] = wsl + 2 * WN2;  ca.n2[3] = WN2;
    ca.src[4] = Wo;    ca.dh[4] = wsh + 3 * WN2; ca.dl[4] = wsl + 3 * WN2;  ca.n2[4] = WN2;
    split_k<<<dim3(1024, 5), 256>>>(ca);

    GArgs qkv;
    qkv.Ah = xh; qkv.Wh = wsh; qkv.Wl = wsl;
    qkv.bias[0] = bq; qkv.bias[1] = bk; qkv.bias[2] = bv;
    qkv.oh[0] = qh; qkv.oh[1] = kh; qkv.oh[2] = vh;
    qkv.C = nullptr;
    gemm_mma<1><<<dim3(Dn / 128, (Bn * Sn) / 128, 3), 256, GEMM_SMEM>>>(qkv);

    attn_k<<<dim3(8, Bn * Hn), 256, ATTN_SMEM>>>(
        qh, kh, kl, vh, wts, aoh);

    GArgs og;
    og.Ah = aoh; og.Wh = wsh + 3 * WN2; og.Wl = wsl + 3 * WN2;
    og.bias[0] = bo; og.bias[1] = bo; og.bias[2] = bo;
    og.oh[0] = og.oh[1] = og.oh[2] = nullptr;
    og.C = out;
    gemm_mma<0><<<dim3(Dn / 128, (Bn * Sn) / 128, 1), 256, GEMM_SMEM>>>(og);
}

// round 17
// speedup vs baseline: 1.2277x; 1.0653x over previous
#include <cuda_runtime.h>
#include <cuda_fp16.h>
#include <cstdint>

#define Bn 2
#define Hn 16
#define Sn 2048
#define Dn 1024
#define HDn 64
#define SC2 (0.125f * 1.44269504088896340736f)

typedef unsigned long long u64;
typedef unsigned int u32;

#define XN2 2097152   // 4096*512
#define WN2 524288    // 1024*512
static __device__ u32 g_xh[XN2];
static __device__ u32 g_wsh[4 * WN2], g_wsl[4 * WN2];
static __device__ u32 g_qh[XN2];
static __device__ u32 g_kh[XN2], g_kl[XN2];
static __device__ u32 g_vh[XN2];
static __device__ u32 g_aoh[XN2];

__device__ __forceinline__ float ex2f_(float x) {
    float y; asm("ex2.approx.f32 %0, %1;" : "=f"(y) : "f"(x)); return y;
}
__device__ __forceinline__ u32 smem_u32(const void* p) {
    u32 a; asm("{ .reg .u64 t; cvta.to.shared.u64 t, %1; cvt.u32.u64 %0, t; }" : "=r"(a) : "l"(p));
    return a;
}
__device__ __forceinline__ u32 f16pack(float a, float b) {
    __half2 h = __floats2half2_rn(a, b);
    return *(u32*)&h;
}
__device__ __forceinline__ float f16lo(u32 h) {
    return __half2float(__ushort_as_half((unsigned short)(h & 0xffffu)));
}
__device__ __forceinline__ float f16hi(u32 h) {
    return __half2float(__ushort_as_half((unsigned short)(h >> 16)));
}
__device__ __forceinline__ void mma16816(float* d, const u32* a, const u32* b) {
    asm volatile(
        "mma.sync.aligned.m16n8k16.row.col.f32.f16.f16.f32 "
        "{%0,%1,%2,%3}, {%4,%5,%6,%7}, {%8,%9}, {%0,%1,%2,%3};"
        : "+f"(d[0]), "+f"(d[1]), "+f"(d[2]), "+f"(d[3])
        : "r"(a[0]), "r"(a[1]), "r"(a[2]), "r"(a[3]), "r"(b[0]), "r"(b[1]));
}
__device__ __forceinline__ void ldsm4(u32* r, u32 addr) {
    asm volatile("ldmatrix.sync.aligned.m8n8.x4.shared.b16 {%0,%1,%2,%3}, [%4];"
        : "=r"(r[0]), "=r"(r[1]), "=r"(r[2]), "=r"(r[3]) : "r"(addr));
}
__device__ __forceinline__ void ldsm4t(u32* r, u32 addr) {
    asm volatile("ldmatrix.sync.aligned.m8n8.x4.trans.shared.b16 {%0,%1,%2,%3}, [%4];"
        : "=r"(r[0]), "=r"(r[1]), "=r"(r[2]), "=r"(r[3]) : "r"(addr));
}
__device__ __forceinline__ void cpa16(u32 dst, const void* src) {
    asm volatile("cp.async.cg.shared.global [%0], [%1], 16;" :: "r"(dst), "l"(src));
}
#define CP_COMMIT() asm volatile("cp.async.commit_group;" ::: "memory")
#define WAITG0() asm volatile("cp.async.wait_group 0;" ::: "memory")
#define WAITG1() asm volatile("cp.async.wait_group 1;" ::: "memory")

// ---------------------------------------------------------------------------
struct CArgs {
    const float* src[5];
    u32* dh[5];
    u32* dl[5];
    int n2[5];
};
__global__ void __launch_bounds__(256) split_k(CArgs ca)
{
    const int z = blockIdx.y;
    const float* __restrict__ s = ca.src[z];
    u32* __restrict__ dh = ca.dh[z];
    u32* __restrict__ dl = ca.dl[z];
    const int n2 = ca.n2[z];
    for (int i = blockIdx.x * 256 + threadIdx.x; i < n2; i += gridDim.x * 256) {
        float2 v = *(const float2*)(s + 2 * i);
        u32 h = f16pack(v.x, v.y);
        dh[i] = h;
        if (dl) dl[i] = f16pack(v.x - f16lo(h), v.y - f16hi(h));
    }
}

// ---------------------------------------------------------------------------
// fp16 2-product GEMM (R10 exact: K-chunk 32, 3-stage cp.async, 2 CTA/SM).
// ---------------------------------------------------------------------------
#define GKH 40
#define GT_AH 0
#define GT_WH 10240
#define GT_WL 20480
#define GSTAGE 30720
#define GNS 3
#define GEMM_SMEM (512 + GNS * GSTAGE)   // 92672

struct GArgs {
    const u32 *Ah, *Wh, *Wl;
    const float* bias[3];
    u32 *oh[3];
    float* C;
};

template <int OUT_SPLIT>
__global__ void __launch_bounds__(256, 2) gemm_mma(GArgs ga)
{
    extern __shared__ char smem[];
    const u32 sbase = smem_u32(smem);
    float* sbias = (float*)smem;

    const int z    = blockIdx.z;
    const int tid  = threadIdx.x;
    const int lane = tid & 31;
    const int wid  = tid >> 5;
    const int n0   = blockIdx.x * 128;
    const int m0   = blockIdx.y * 128;
    const int wm   = (wid & 1) * 64;
    const int wn   = (wid >> 1) * 32;

    const u32* __restrict__ Ah = ga.Ah;
    const u32* __restrict__ Wh = ga.Wh + (size_t)z * WN2;
    const u32* __restrict__ Wl = ga.Wl + (size_t)z * WN2;

    if (tid < 128) sbias[tid] = ga.bias[z][n0 + tid];

    float acc[4][4][4];
#pragma unroll
    for (int i = 0; i < 4; i++)
#pragma unroll
        for (int j = 0; j < 4; j++)
#pragma unroll
            for (int c = 0; c < 4; c++) acc[i][j][c] = 0.f;

    const int lrow = tid >> 1;
    const int lh   = tid & 1;
    const size_t abase = (size_t)(m0 + lrow) * 512 + lh * 8;
    const size_t wbase = (size_t)(n0 + lrow) * 512 + lh * 8;
    const u32 sobase = lrow * 80 + lh * 32;

    auto load_stage = [&](int t, int slot) {
        const u32 so = sbase + 512 + slot * GSTAGE + sobase;
        const size_t ka = abase + t * 16;
        const size_t kw = wbase + t * 16;
        cpa16(so + GT_AH,      Ah + ka);
        cpa16(so + GT_AH + 16, Ah + ka + 4);
        cpa16(so + GT_WH,      Wh + kw);
        cpa16(so + GT_WH + 16, Wh + kw + 4);
        cpa16(so + GT_WL,      Wl + kw);
        cpa16(so + GT_WL + 16, Wl + kw + 4);
    };

    const int a_r  = wm + (lane & 15);
    const int b_r4 = wn + (lane & 7) + ((lane & 16) ? 8 : 0);

    auto mma_stage = [&](int slot) {
        const u32 sb = sbase + 512 + slot * GSTAGE;
#pragma unroll
        for (int ks = 0; ks < 2; ks++) {
            const int acol  = ks * 16 + ((lane & 16) ? 8 : 0);
            const int bcol4 = ks * 16 + ((lane & 8) ? 8 : 0);
            u32 ah[4][4];
#pragma unroll
            for (int mt = 0; mt < 4; mt++)
                ldsm4(ah[mt], sb + GT_AH + (u32)((a_r + mt * 16) * (GKH * 2) + acol * 2));
            u32 bhq[2][4], blq[2][4];
#pragma unroll
            for (int np = 0; np < 2; np++) {
                u32 o = (u32)((b_r4 + np * 16) * (GKH * 2) + bcol4 * 2);
                ldsm4(bhq[np], sb + GT_WH + o);
                ldsm4(blq[np], sb + GT_WL + o);
            }
#pragma unroll
            for (int mt = 0; mt < 4; mt++)
#pragma unroll
                for (int nt = 0; nt < 4; nt++) {
                    const u32* bh_ = &bhq[nt >> 1][(nt & 1) * 2];
                    const u32* bl_ = &blq[nt >> 1][(nt & 1) * 2];
                    mma16816(acc[mt][nt], ah[mt], bh_);
                    mma16816(acc[mt][nt], ah[mt], bl_);
                }
        }
    };

    const int NT = Dn / 32;
    load_stage(0, 0); CP_COMMIT();
    load_stage(1, 1); CP_COMMIT();

    for (int t = 0; t < NT; t++) {
        if (t + 1 < NT) { WAITG1(); } else { WAITG0(); }
        __syncthreads();
        if (t + 2 < NT) { load_stage(t + 2, (t + 2) % GNS); CP_COMMIT(); }
        mma_stage(t % GNS);
    }

    const int g   = lane >> 2;
    const int tig = lane & 3;
    const float osc = (OUT_SPLIT && z == 0) ? SC2 : 1.0f;
#pragma unroll
    for (int mt = 0; mt < 4; mt++) {
#pragma unroll
        for (int nt = 0; nt < 4; nt++) {
            int coll = wn + nt * 8 + tig * 2;
            int col  = n0 + coll;
            float bx = sbias[coll], by = sbias[coll + 1];
            int r0 = m0 + wm + mt * 16 + g;
            int r1 = r0 + 8;
            float x0 = (acc[mt][nt][0] + bx) * osc, y0 = (acc[mt][nt][1] + by) * osc;
            float x1 = (acc[mt][nt][2] + bx) * osc, y1 = (acc[mt][nt][3] + by) * osc;
            if (OUT_SPLIT) {
                u32* oh = ga.oh[z];
                u32* ol = (z == 1) ? g_kl : nullptr;
                int h = col >> 6, cu = (col & 63) >> 1;
                {
                    int b = r0 >> 11, s = r0 & 2047;
                    size_t idx = ((size_t)((b << 4) + h) * Sn + s) * 32 + cu;
                    u32 hh = f16pack(x0, y0);
                    oh[idx] = hh;
                    if (ol) ol[idx] = f16pack(x0 - f16lo(hh), y0 - f16hi(hh));
                }
                {
                    int b = r1 >> 11, s = r1 & 2047;
                    size_t idx = ((size_t)((b << 4) + h) * Sn + s) * 32 + cu;
                    u32 hh = f16pack(x1, y1);
                    oh[idx] = hh;
                    if (ol) ol[idx] = f16pack(x1 - f16lo(hh), y1 - f16hi(hh));
                }
            } else {
                *(float2*)&ga.C[(size_t)r0 * Dn + col] = make_float2(x0, y0);
                *(float2*)&ga.C[(size_t)r1 * Dn + col] = make_float2(x1, y1);
            }
        }
    }
}

// ---------------------------------------------------------------------------
// Attention (R16 two-phase, paired q-tiles), phase 1 now K-HI-ONLY:
//   phase 1: stream K(hi), QK(hi) + exp, row sums only (half MMAs & traffic).
//   phase 2: full hi+lo QK, write FINAL normalized weights once (.cs), PV.
// ---------------------------------------------------------------------------
#define PADH 72
#define PADB (PADH * 2)
#define TILE_HB (128 * PADB)            // 18432
#define QA_OFF 0
#define QB_OFF 18432
#define KS(st) (36864 + (st) * 36864)   // hi +0, lo +18432
#define VS(st) (110592 + (st) * 18432)
#define ATTN_SMEM 147456

__global__ void __launch_bounds__(256) attn_k(
    const u32* __restrict__ qh,
    const u32* __restrict__ kh, const u32* __restrict__ kl,
    const u32* __restrict__ vh,
    float* __restrict__ wout, u32* __restrict__ aoh)
{
    extern __shared__ char smem[];
    const u32 sb = smem_u32(smem);

    const int tid  = threadIdx.x;
    const int lane = tid & 31;
    const int wid  = tid >> 5;
    const int qbA  = blockIdx.x;          // 0..7
    const int qbB  = 15 - qbA;            // 15..8
    const int bh   = blockIdx.y;
    const int qA0  = qbA * 128;
    const int qB0  = qbB * 128;
    const int g    = lane >> 2;
    const int tig  = lane & 3;
    const float NEG_INF = __int_as_float(0xff800000);

    const int lrow = tid >> 1;
    const int lseg = (tid & 1) * 16;

    auto load_q = [&](int q0, u32 qoff) {
        const size_t gidx = ((size_t)bh * Sn + q0 + lrow) * 32 + lseg;
        const u32 so = sb + qoff + lrow * PADB + lseg * 4;
#pragma unroll
        for (int j = 0; j < 4; j++) cpa16(so + j * 16, qh + gidx + j * 4);
    };
    auto load_k1 = [&](int kt) {          // hi only (phase 1)
        const size_t gidx = ((size_t)bh * Sn + kt * 128 + lrow) * 32 + lseg;
        const u32 so = sb + KS(kt & 1) + lrow * PADB + lseg * 4;
#pragma unroll
        for (int j = 0; j < 4; j++) cpa16(so + j * 16, kh + gidx + j * 4);
    };
    auto load_k2 = [&](int kt) {          // hi + lo (phase 2)
        const size_t gidx = ((size_t)bh * Sn + kt * 128 + lrow) * 32 + lseg;
        const u32 so = sb + KS(kt & 1) + lrow * PADB + lseg * 4;
#pragma unroll
        for (int j = 0; j < 4; j++) {
            cpa16(so + j * 16,           kh + gidx + j * 4);
            cpa16(so + TILE_HB + j * 16, kl + gidx + j * 4);
        }
    };
    auto load_v1 = [&](int kt) {
        const size_t gidx = ((size_t)bh * Sn + kt * 128 + lrow) * 32 + lseg;
        const u32 so = sb + VS(kt & 1) + lrow * PADB + lseg * 4;
#pragma unroll
        for (int j = 0; j < 4; j++) cpa16(so + j * 16, vh + gidx + j * 4);
    };

    const int r0l = wid * 16 + g;

    // full-precision scores (phase 2)
    auto qk_scores = [&](u32 qoff, int kt, bool diag, float acc[16][4]) {
#pragma unroll
        for (int nt = 0; nt < 16; nt++)
#pragma unroll
            for (int c = 0; c < 4; c++) acc[nt][c] = 0.f;
        const u32 a_base  = sb + qoff + (wid * 16 + (lane & 15)) * PADB + (((lane >> 4) << 3)) * 2;
        const u32 b_base4 = sb + KS(kt & 1) + ((lane & 7) + ((lane & 16) ? 8 : 0)) * PADB
                          + (((lane >> 3) & 1) << 3) * 2;
#pragma unroll
        for (int kc = 0; kc < 4; kc++) {
            u32 ah[4];
            ldsm4(ah, a_base + kc * 32);
#pragma unroll
            for (int np = 0; np < 8; np++) {
                u32 bhq[4], blq[4];
                u32 bo = b_base4 + np * 16 * PADB + kc * 32;
                ldsm4(bhq, bo);
                ldsm4(blq, bo + TILE_HB);
                mma16816(acc[2 * np],     ah, bhq);
                mma16816(acc[2 * np],     ah, blq);
                mma16816(acc[2 * np + 1], ah, bhq + 2);
                mma16816(acc[2 * np + 1], ah, blq + 2);
            }
        }
        if (diag) {
#pragma unroll
            for (int nt = 0; nt < 16; nt++) {
                int c0 = nt * 8 + tig * 2;
                if (c0 > r0l)         acc[nt][0] = NEG_INF;
                if (c0 + 1 > r0l)     acc[nt][1] = NEG_INF;
                if (c0 > r0l + 8)     acc[nt][2] = NEG_INF;
                if (c0 + 1 > r0l + 8) acc[nt][3] = NEG_INF;
            }
        }
    };

    // hi-only scores (phase 1, sums only)
    auto qk_scores_hi = [&](u32 qoff, int kt, bool diag, float acc[16][4]) {
#pragma unroll
        for (int nt = 0; nt < 16; nt++)
#pragma unroll
            for (int c = 0; c < 4; c++) acc[nt][c] = 0.f;
        const u32 a_base  = sb + qoff + (wid * 16 + (lane & 15)) * PADB + (((lane >> 4) << 3)) * 2;
        const u32 b_base4 = sb + KS(kt & 1) + ((lane & 7) + ((lane & 16) ? 8 : 0)) * PADB
                          + (((lane >> 3) & 1) << 3) * 2;
#pragma unroll
        for (int kc = 0; kc < 4; kc++) {
            u32 ah[4];
            ldsm4(ah, a_base + kc * 32);
#pragma unroll
            for (int np = 0; np < 8; np++) {
                u32 bhq[4];
                ldsm4(bhq, b_base4 + np * 16 * PADB + kc * 32);
                mma16816(acc[2 * np],     ah, bhq);
                mma16816(acc[2 * np + 1], ah, bhq + 2);
            }
        }
        if (diag) {
#pragma unroll
            for (int nt = 0; nt < 16; nt++) {
                int c0 = nt * 8 + tig * 2;
                if (c0 > r0l)         acc[nt][0] = NEG_INF;
                if (c0 + 1 > r0l)     acc[nt][1] = NEG_INF;
                if (c0 > r0l + 8)     acc[nt][2] = NEG_INF;
                if (c0 + 1 > r0l + 8) acc[nt][3] = NEG_INF;
            }
        }
    };

    float rsA0 = 0.f, rsA1 = 0.f, rsB0 = 0.f, rsB1 = 0.f;

    auto sum_only = [&](u32 qoff, int kt, bool diag, float& rs0, float& rs1) {
        float acc[16][4];
        qk_scores_hi(qoff, kt, diag, acc);
#pragma unroll
        for (int nt = 0; nt < 16; nt++) {
            rs0 += ex2f_(acc[nt][0]) + ex2f_(acc[nt][1]);
            rs1 += ex2f_(acc[nt][2]) + ex2f_(acc[nt][3]);
        }
    };

    // ---- Phase 1: row sums (K hi only, no stores) ----
    load_q(qA0, QA_OFF);
    load_q(qB0, QB_OFF);
    load_k1(0);
    CP_COMMIT();

    for (int kt = 0; kt <= qbB; kt++) {
        WAITG0();
        __syncthreads();
        if (kt < qbB) { load_k1(kt + 1); CP_COMMIT(); }
        sum_only(QB_OFF, kt, kt == qbB, rsB0, rsB1);
        if (kt <= qbA)
            sum_only(QA_OFF, kt, kt == qbA, rsA0, rsA1);
    }

    rsA0 += __shfl_xor_sync(0xffffffffu, rsA0, 1);
    rsA0 += __shfl_xor_sync(0xffffffffu, rsA0, 2);
    rsA1 += __shfl_xor_sync(0xffffffffu, rsA1, 1);
    rsA1 += __shfl_xor_sync(0xffffffffu, rsA1, 2);
    rsB0 += __shfl_xor_sync(0xffffffffu, rsB0, 1);
    rsB0 += __shfl_xor_sync(0xffffffffu, rsB0, 2);
    rsB1 += __shfl_xor_sync(0xffffffffu, rsB1, 1);
    rsB1 += __shfl_xor_sync(0xffffffffu, rsB1, 2);
    const float ilA0 = 1.0f / rsA0, ilA1 = 1.0f / rsA1;
    const float ilB0 = 1.0f / rsB0, ilB1 = 1.0f / rsB1;

    // ---- Phase 2: normalized weights (write-once, .cs) + PV ----
    __syncthreads();
    load_k2(0);
    load_v1(0);
    CP_COMMIT();

    float oaccA[8][4], oaccB[8][4];
#pragma unroll
    for (int v = 0; v < 8; v++)
#pragma unroll
        for (int c = 0; c < 4; c++) { oaccA[v][c] = 0.f; oaccB[v][c] = 0.f; }

    float* wpA0 = wout + (size_t)bh * Sn * Sn + (size_t)(qA0 + r0l) * Sn;
    float* wpA1 = wpA0 + 8 * Sn;
    float* wpB0 = wout + (size_t)bh * Sn * Sn + (size_t)(qB0 + r0l) * Sn;
    float* wpB1 = wpB0 + 8 * Sn;

    auto process = [&](u32 qoff, int kt, bool diag, float* wp0, float* wp1,
                       float (&oacc)[8][4], float il0, float il1) {
        float acc[16][4];
        qk_scores(qoff, kt, diag, acc);
#pragma unroll
        for (int nt = 0; nt < 16; nt++) {
            float p0 = ex2f_(acc[nt][0]);
            float p1 = ex2f_(acc[nt][1]);
            float p2 = ex2f_(acc[nt][2]);
            float p3 = ex2f_(acc[nt][3]);
            acc[nt][0] = p0; acc[nt][1] = p1; acc[nt][2] = p2; acc[nt][3] = p3;
            int c0 = kt * 128 + nt * 8 + tig * 2;
            __stcs((float2*)(wp0 + c0), make_float2(p0 * il0, p1 * il0));
            __stcs((float2*)(wp1 + c0), make_float2(p2 * il1, p3 * il1));
        }
        const u32 v_base4 = sb + VS(kt & 1) + (lane & 15) * PADB + ((lane & 16) ? 16 : 0);
#pragma unroll
        for (int kc = 0; kc < 8; kc++) {
            u32 aph[4];
            aph[0] = f16pack(acc[2 * kc][0],     acc[2 * kc][1]);
            aph[1] = f16pack(acc[2 * kc][2],     acc[2 * kc][3]);
            aph[2] = f16pack(acc[2 * kc + 1][0], acc[2 * kc + 1][1]);
            aph[3] = f16pack(acc[2 * kc + 1][2], acc[2 * kc + 1][3]);
            const u32 vb = v_base4 + kc * 16 * PADB;
#pragma unroll
            for (int vp = 0; vp < 4; vp++) {
                u32 vh4[4];
                ldsm4t(vh4, vb + vp * 32);
                mma16816(oacc[2 * vp],     aph, vh4);
                mma16816(oacc[2 * vp + 1], aph, vh4 + 2);
            }
        }
    };

    for (int kt = 0; kt <= qbB; kt++) {
        WAITG0();
        __syncthreads();
        if (kt < qbB) {
            load_k2(kt + 1);
            load_v1(kt + 1);
            CP_COMMIT();
        }
        process(QB_OFF, kt, kt == qbB, wpB0, wpB1, oaccB, ilB0, ilB1);
        if (kt <= qbA)
            process(QA_OFF, kt, kt == qbA, wpA0, wpA1, oaccA, ilA0, ilA1);
    }

    // scale outputs (PV used unnormalized p)
#pragma unroll
    for (int vt = 0; vt < 8; vt++) {
        oaccA[vt][0] *= ilA0; oaccA[vt][1] *= ilA0;
        oaccA[vt][2] *= ilA1; oaccA[vt][3] *= ilA1;
        oaccB[vt][0] *= ilB0; oaccB[vt][1] *= ilB0;
        oaccB[vt][2] *= ilB1; oaccB[vt][3] *= ilB1;
    }

    // zero-fill masked regions for both tiles
    {
        const int row = tid >> 1;
        const float4 z4 = make_float4(0.f, 0.f, 0.f, 0.f);
        {
            const int zw = (15 - qbA) * 128;
            const int half = (tid & 1) * (zw >> 1);
            float* p = wout + (size_t)bh * Sn * Sn + (size_t)(qA0 + row) * Sn
                     + (qbA + 1) * 128 + half;
            for (int c = 0; c < (zw >> 1); c += 4) __stcs((float4*)(p + c), z4);
        }
        if (qbB < 15) {
            const int zw = (15 - qbB) * 128;
            const int half = (tid & 1) * (zw >> 1);
            float* p = wout + (size_t)bh * Sn * Sn + (size_t)(qB0 + row) * Sn
                     + (qbB + 1) * 128 + half;
            for (int c = 0; c < (zw >> 1); c += 4) __stcs((float4*)(p + c), z4);
        }
    }

    // attention outputs -> fp16 hi flat [4096][512 u32]
    {
        const size_t tA0 = ((size_t)(bh >> 4) * Sn + qA0 + r0l) * 512 + (bh & 15) * 32;
        const size_t tA1 = tA0 + 8 * 512;
        const size_t tB0 = ((size_t)(bh >> 4) * Sn + qB0 + r0l) * 512 + (bh & 15) * 32;
        const size_t tB1 = tB0 + 8 * 512;
#pragma unroll
        for (int vt = 0; vt < 8; vt++) {
            int c = vt * 4 + tig;
            aoh[tA0 + c] = f16pack(oaccA[vt][0], oaccA[vt][1]);
            aoh[tA1 + c] = f16pack(oaccA[vt][2], oaccA[vt][3]);
            aoh[tB0 + c] = f16pack(oaccB[vt][0], oaccB[vt][1]);
            aoh[tB1 + c] = f16pack(oaccB[vt][2], oaccB[vt][3]);
        }
    }
}

// ---------------------------------------------------------------------------
extern "C" void kernel_launch(void* const* d_in, const int* in_sizes, int n_in,
                              void* d_out, int out_size)
{
    const float* query = (const float*)d_in[0];
    const float* Wq    = (const float*)d_in[1];
    const float* bq    = (const float*)d_in[2];
    const float* Wk    = (const float*)d_in[3];
    const float* bk    = (const float*)d_in[4];
    const float* Wv    = (const float*)d_in[5];
    const float* bv    = (const float*)d_in[6];
    const float* Wo    = (const float*)d_in[7];
    const float* bo    = (const float*)d_in[8];

    float* out = (float*)d_out;
    float* wts = out + (size_t)Bn * Sn * Dn;

    u32 *xh, *wsh, *wsl, *qh, *kh, *kl, *vh, *aoh;
    cudaGetSymbolAddress((void**)&xh,  g_xh);
    cudaGetSymbolAddress((void**)&wsh, g_wsh); cudaGetSymbolAddress((void**)&wsl, g_wsl);
    cudaGetSymbolAddress((void**)&qh,  g_qh);
    cudaGetSymbolAddress((void**)&kh,  g_kh);  cudaGetSymbolAddress((void**)&kl,  g_kl);
    cudaGetSymbolAddress((void**)&vh,  g_vh);
    cudaGetSymbolAddress((void**)&aoh, g_aoh);

    cudaFuncSetAttribute(attn_k, cudaFuncAttributeMaxDynamicSharedMemorySize, ATTN_SMEM);
    cudaFuncSetAttribute(gemm_mma<1>, cudaFuncAttributeMaxDynamicSharedMemorySize, GEMM_SMEM);
    cudaFuncSetAttribute(gemm_mma<0>, cudaFuncAttributeMaxDynamicSharedMemorySize, GEMM_SMEM);

    CArgs ca;
    ca.src[0] = query; ca.dh[0] = xh;            ca.dl[0] = nullptr;        ca.n2[0] = XN2;
    ca.src[1] = Wq;    ca.dh[1] = wsh;           ca.dl[1] = wsl;            ca.n2[1] = WN2;
    ca.src[2] = Wk;    ca.dh[2] = wsh + WN2;     ca.dl[2] = wsl + WN2;      ca.n2[2] = WN2;
    ca.src[3] = Wv;    ca.dh[3] = wsh + 2 * WN2; ca.dl[3] = wsl + 2 * WN2;  ca.n2[3] = WN2;
    ca.src[4] = Wo;    ca.dh[4] = wsh + 3 * WN2; ca.dl[4] = wsl + 3 * WN2;  ca.n2[4] = WN2;
    split_k<<<dim3(1024, 5), 256>>>(ca);

    GArgs qkv;
    qkv.Ah = xh; qkv.Wh = wsh; qkv.Wl = wsl;
    qkv.bias[0] = bq; qkv.bias[1] = bk; qkv.bias[2] = bv;
    qkv.oh[0] = qh; qkv.oh[1] = kh; qkv.oh[2] = vh;
    qkv.C = nullptr;
    gemm_mma<1><<<dim3(Dn / 128, (Bn * Sn) / 128, 3), 256, GEMM_SMEM>>>(qkv);

    attn_k<<<dim3(8, Bn * Hn), 256, ATTN_SMEM>>>(
        qh, kh, kl, vh, wts, aoh);

    GArgs og;
    og.Ah = aoh; og.Wh = wsh + 3 * WN2; og.Wl = wsl + 3 * WN2;
    og.bias[0] = bo; og.bias[1] = bo; og.bias[2] = bo;
    og.oh[0] = og.oh[1] = og.oh[2] = nullptr;
    og.C = out;
    gemm_mma<0><<<dim3(Dn / 128, (Bn * Sn) / 128, 1), 256, GEMM_SMEM>>>(og);
}